// round 5
// baseline (speedup 1.0000x reference)
#include <cuda_runtime.h>
#include <cuda_fp16.h>
#include <cstdint>

// ---------------------------------------------------------------------------
// S5 SSM: ys = 2*Re( scan(Lam_bar, B_bar@u) @ C^T ) + d*u
// GEMMs: mma.sync fp16 hi/lo split, 3 terms:
//    main AhBh -> f32 accum, cross AhBl'+Al'Bh -> shared f16 accum (lo pre-
//    scaled by 2048; epilogue adds accC/2048)
// Scan: single-pass decoupled-lookback (fused local scan + carry + fp16 split)
// ---------------------------------------------------------------------------

#define L_SEQ   32768
#define H_FEAT  512
#define P_STATE 256
#define N2      512
#define C_CHUNKS 512
#define T_CHUNK  64
#define SQ_POW   6
#define INV2048 (1.0f / 2048.0f)

#define BM 128
#define BN 128
#define NCH 16             // 512 / 32
#define ROWB 80            // padded smem row bytes (64B data + 16B pad)
#define OP_BYTES (128 * ROWB)          // 10240 per operand tile
#define STG_BYTES (4 * OP_BYTES)       // Ah, Al, Bh, Bl
#define NSTAGE 3
#define SMEMB (NSTAGE * STG_BYTES)     // 122880

// Scratch (static __device__; no cudaMalloc allowed)
__device__ float2 g_Bu[L_SEQ * P_STATE];               // 64 MB
__device__ __half g_Ahi[L_SEQ * N2];                   // 32 MB
__device__ __half g_Alo[L_SEQ * N2];                   // 32 MB (scaled x2048)
__device__ __half g_W1hi[N2 * H_FEAT], g_W1lo[N2 * H_FEAT];
__device__ __half g_W2hi[H_FEAT * N2], g_W2lo[H_FEAT * N2];
__device__ float2 g_a[P_STATE];
__device__ float2 g_aT[P_STATE];
__device__ float2 g_Bscale[P_STATE];
__device__ float2 g_end[C_CHUNKS * P_STATE];
__device__ int    g_flags[C_CHUNKS];

__device__ __forceinline__ float2 cmul(float2 a, float2 b) {
    return make_float2(a.x * b.x - a.y * b.y, a.x * b.y + a.y * b.x);
}

__device__ __forceinline__ uint32_t smem_u32(const void* p) {
    uint32_t a;
    asm("{ .reg .u64 t; cvta.to.shared.u64 t, %1; cvt.u32.u64 %0, t; }"
        : "=r"(a) : "l"(p));
    return a;
}
__device__ __forceinline__ void cp16(uint32_t dst, const void* src) {
    asm volatile("cp.async.cg.shared.global [%0], [%1], 16;" :: "r"(dst), "l"(src));
}
__device__ __forceinline__ void ldsm4(uint32_t* r, uint32_t addr) {
    asm volatile("ldmatrix.sync.aligned.m8n8.x4.shared.b16 {%0,%1,%2,%3}, [%4];"
                 : "=r"(r[0]), "=r"(r[1]), "=r"(r[2]), "=r"(r[3]) : "r"(addr));
}
// f32-accum fp16 MMA
__device__ __forceinline__ void mma_f32(float* d, const uint32_t* a,
                                        uint32_t b0, uint32_t b1) {
    asm volatile(
        "mma.sync.aligned.m16n8k16.row.col.f32.f16.f16.f32 "
        "{%0,%1,%2,%3}, {%4,%5,%6,%7}, {%8,%9}, {%0,%1,%2,%3};"
        : "+f"(d[0]), "+f"(d[1]), "+f"(d[2]), "+f"(d[3])
        : "r"(a[0]), "r"(a[1]), "r"(a[2]), "r"(a[3]), "r"(b0), "r"(b1));
}
// f16-accum fp16 MMA
__device__ __forceinline__ void mma_f16(uint32_t* d, const uint32_t* a,
                                        uint32_t b0, uint32_t b1) {
    asm volatile(
        "mma.sync.aligned.m16n8k16.row.col.f16.f16.f16.f16 "
        "{%0,%1}, {%2,%3,%4,%5}, {%6,%7}, {%0,%1};"
        : "+r"(d[0]), "+r"(d[1])
        : "r"(a[0]), "r"(a[1]), "r"(a[2]), "r"(a[3]), "r"(b0), "r"(b1));
}

// ---------------------------------------------------------------------------
__global__ void prep_params(const float* __restrict__ lr,
                            const float* __restrict__ li,
                            const float* __restrict__ delta) {
    int p = threadIdx.x;
    float step = expf(delta[p]);
    float hs = 0.5f * step;
    float dr = 1.0f - hs * lr[p];
    float di = -hs * li[p];
    float inv = 1.0f / (dr * dr + di * di);
    float2 BL = make_float2(dr * inv, -di * inv);
    float2 num = make_float2(1.0f + hs * lr[p], hs * li[p]);
    float2 a = cmul(BL, num);
    g_a[p] = a;
    g_Bscale[p] = make_float2(BL.x * step, BL.y * step);
    float2 t = a;
    #pragma unroll
    for (int i = 0; i < SQ_POW; i++) t = cmul(t, t);
    g_aT[p] = t;
}

__global__ void zero_flags() { g_flags[threadIdx.x] = 0; }

__device__ __forceinline__ void store_split(__half* hi, __half* lo,
                                            int idx, float v) {
    __half h = __float2half_rn(v);
    hi[idx] = h;
    lo[idx] = __float2half_rn((v - __half2float(h)) * 2048.0f);
}

__global__ void prep_weights(const float* __restrict__ b,
                             const float* __restrict__ c) {
    int p = blockIdx.x;        // 0..255
    int h = threadIdx.x;       // 0..511
    float2 bs = g_Bscale[p];
    float br = b[(p * H_FEAT + h) * 2 + 0];
    float bi = b[(p * H_FEAT + h) * 2 + 1];
    store_split(g_W1hi, g_W1lo, (2 * p) * H_FEAT + h, bs.x * br - bs.y * bi);
    store_split(g_W1hi, g_W1lo, (2 * p + 1) * H_FEAT + h, bs.x * bi + bs.y * br);
    store_split(g_W2hi, g_W2lo, h * N2 + 2 * p,      2.0f * c[(h * P_STATE + p) * 2 + 0]);
    store_split(g_W2hi, g_W2lo, h * N2 + 2 * p + 1, -2.0f * c[(h * P_STATE + p) * 2 + 1]);
}

// fp32 -> fp16 hi + scaled-lo split (grid-stride, float4)
__global__ void convert_split(const float4* __restrict__ src,
                              uint2* __restrict__ hi, uint2* __restrict__ lo, int n4) {
    int stride = gridDim.x * blockDim.x;
    for (int i = blockIdx.x * blockDim.x + threadIdx.x; i < n4; i += stride) {
        float4 v = src[i];
        __half2 h0 = __floats2half2_rn(v.x, v.y);
        __half2 h1 = __floats2half2_rn(v.z, v.w);
        float2 f0 = __half22float2(h0);
        float2 f1 = __half22float2(h1);
        __half2 l0 = __floats2half2_rn((v.x - f0.x) * 2048.0f, (v.y - f0.y) * 2048.0f);
        __half2 l1 = __floats2half2_rn((v.z - f1.x) * 2048.0f, (v.w - f1.y) * 2048.0f);
        hi[i] = make_uint2(*(uint32_t*)&h0, *(uint32_t*)&h1);
        lo[i] = make_uint2(*(uint32_t*)&l0, *(uint32_t*)&l1);
    }
}

// ---------------------------------------------------------------------------
// fp16 split GEMM: C[M,512] = (Ah+Al/2048)[M,K] x (Bh+Bl/2048)[N,K]^T
// block 128x128, 256 thr, warp 32x64; main f32-acc, cross f16-acc
// ---------------------------------------------------------------------------
template <bool EPI>
__global__ void __launch_bounds__(256, 1)
gemm_fp16(const __half* __restrict__ Ahi, const __half* __restrict__ Alo,
          const __half* __restrict__ Bhi, const __half* __restrict__ Blo,
          float* __restrict__ Cout, const float* __restrict__ U,
          const float* __restrict__ D) {
    extern __shared__ char smem[];
    const uint32_t sb = smem_u32(smem);
    const int tid = threadIdx.x;
    const int wid = tid >> 5, lane = tid & 31;
    const int warpM = wid & 3, warpN = wid >> 2;       // 4x2 warp grid
    const int bm = blockIdx.y * BM;
    const int bn = blockIdx.x * BN;

    const char* bases[4] = {
        (const char*)Ahi + (size_t)bm * 1024,
        (const char*)Alo + (size_t)bm * 1024,
        (const char*)Bhi + (size_t)bn * 1024,
        (const char*)Blo + (size_t)bn * 1024 };

    auto load_chunk = [&](int kt, int st) {
        const uint32_t base = sb + st * STG_BYTES;
        const int kb = kt * 64;                        // byte offset into row
        const int s = tid & 3;
        #pragma unroll
        for (int j = 0; j < 8; j++) {
            const int op = j >> 1;
            const int r = (tid >> 2) + ((j & 1) << 6);
            cp16(base + op * OP_BYTES + r * ROWB + s * 16,
                 bases[op] + (size_t)r * 1024 + kb + s * 16);
        }
        asm volatile("cp.async.commit_group;");
    };

    load_chunk(0, 0);
    load_chunk(1, 1);

    float acc[2][8][4];
    uint32_t accC[2][8][2];
    #pragma unroll
    for (int im = 0; im < 2; im++)
        #pragma unroll
        for (int in = 0; in < 8; in++) {
            #pragma unroll
            for (int q = 0; q < 4; q++) acc[im][in][q] = 0.0f;
            accC[im][in][0] = 0u; accC[im][in][1] = 0u;
        }

    const uint32_t a_lo = (lane & 15) * ROWB + (lane >> 4) * 16;
    const uint32_t b_lo = ((lane & 7) + ((lane >> 4) << 3)) * ROWB +
                          ((lane >> 3) & 1) * 16;

    for (int kt = 0; kt < NCH; kt++) {
        const int st = kt % NSTAGE;
        if (kt == NCH - 1) asm volatile("cp.async.wait_group 0;");
        else               asm volatile("cp.async.wait_group 1;");
        __syncthreads();
        if (kt + 2 < NCH) load_chunk(kt + 2, (kt + 2) % NSTAGE);

        const uint32_t sg = sb + st * STG_BYTES;
        #pragma unroll
        for (int ks = 0; ks < 2; ks++) {
            const uint32_t ksb = ks * 32;
            uint32_t ah[2][4], al[2][4], bh[4][4], bl[4][4];
            #pragma unroll
            for (int im = 0; im < 2; im++) {
                const uint32_t ao = (warpM * 32 + im * 16) * ROWB + a_lo + ksb;
                ldsm4(ah[im], sg + ao);
                ldsm4(al[im], sg + OP_BYTES + ao);
            }
            #pragma unroll
            for (int ip = 0; ip < 4; ip++) {
                const uint32_t bo = (warpN * 64 + ip * 16) * ROWB + b_lo + ksb;
                ldsm4(bh[ip], sg + 2 * OP_BYTES + bo);
                ldsm4(bl[ip], sg + 3 * OP_BYTES + bo);
            }
            // main term: f32 accum
            #pragma unroll
            for (int im = 0; im < 2; im++)
                #pragma unroll
                for (int ip = 0; ip < 4; ip++) {
                    mma_f32(acc[im][2 * ip],     ah[im], bh[ip][0], bh[ip][1]);
                    mma_f32(acc[im][2 * ip + 1], ah[im], bh[ip][2], bh[ip][3]);
                }
            // cross terms: shared f16 accum (both scaled by 2048)
            #pragma unroll
            for (int im = 0; im < 2; im++)
                #pragma unroll
                for (int ip = 0; ip < 4; ip++) {
                    mma_f16(accC[im][2 * ip],     ah[im], bl[ip][0], bl[ip][1]);
                    mma_f16(accC[im][2 * ip + 1], ah[im], bl[ip][2], bl[ip][3]);
                    mma_f16(accC[im][2 * ip],     al[im], bh[ip][0], bh[ip][1]);
                    mma_f16(accC[im][2 * ip + 1], al[im], bh[ip][2], bh[ip][3]);
                }
        }
    }

    #pragma unroll
    for (int im = 0; im < 2; im++) {
        const int row0 = bm + warpM * 32 + im * 16 + (lane >> 2);
        #pragma unroll
        for (int in = 0; in < 8; in++) {
            const int col = bn + warpN * 64 + in * 8 + (lane & 3) * 2;
            float2 c0 = __half22float2(*(__half2*)&accC[im][in][0]);
            float2 c1 = __half22float2(*(__half2*)&accC[im][in][1]);
            float2 v0 = make_float2(fmaf(c0.x, INV2048, acc[im][in][0]),
                                    fmaf(c0.y, INV2048, acc[im][in][1]));
            float2 v1 = make_float2(fmaf(c1.x, INV2048, acc[im][in][2]),
                                    fmaf(c1.y, INV2048, acc[im][in][3]));
            if constexpr (EPI) {
                float2 dv = *(const float2*)&D[col];
                float2 u0 = *(const float2*)&U[(size_t)row0 * H_FEAT + col];
                float2 u1 = *(const float2*)&U[(size_t)(row0 + 8) * H_FEAT + col];
                v0.x = fmaf(dv.x, u0.x, v0.x); v0.y = fmaf(dv.y, u0.y, v0.y);
                v1.x = fmaf(dv.x, u1.x, v1.x); v1.y = fmaf(dv.y, u1.y, v1.y);
            }
            *(float2*)&Cout[(size_t)row0 * H_FEAT + col] = v0;
            *(float2*)&Cout[(size_t)(row0 + 8) * H_FEAT + col] = v1;
        }
    }
}

// ---------------------------------------------------------------------------
// Single-pass scan: local end -> publish -> lookback carry -> rescan + split
// Deterministic: exact arithmetic chain, flags only gate availability.
// ---------------------------------------------------------------------------
__global__ void __launch_bounds__(256) scan_fused() {
    const int p = threadIdx.x;
    const int c = blockIdx.x;
    const float2 a = g_a[p];
    const float2 aT = g_aT[p];
    const size_t base = (size_t)c * T_CHUNK * P_STATE + p;

    // Phase A: local end state (zero init)
    float2 x = make_float2(0.0f, 0.0f);
    #pragma unroll 8
    for (int t = 0; t < T_CHUNK; t++) {
        float2 v = g_Bu[base + (size_t)t * P_STATE];
        x = make_float2(fmaf(a.x, x.x, fmaf(-a.y, x.y, v.x)),
                        fmaf(a.x, x.y, fmaf(a.y, x.x, v.y)));
    }
    g_end[c * P_STATE + p] = x;
    __threadfence();
    __syncthreads();
    if (p == 0) {
        int* fl = &g_flags[c];
        asm volatile("st.release.gpu.global.u32 [%0], %1;" :: "l"(fl), "r"(1) : "memory");
    }

    // Phase B: carry = sum_{j<c} aT^{c-1-j} end_j  via sequential combine
    float2 carry = make_float2(0.0f, 0.0f);
    for (int j = 0; j < c; j++) {
        int f;
        const int* fl = &g_flags[j];
        do {
            asm volatile("ld.acquire.gpu.global.u32 %0, [%1];" : "=r"(f) : "l"(fl) : "memory");
        } while (f == 0);
        float2 e = g_end[j * P_STATE + p];
        float2 t = cmul(aT, carry);
        carry = make_float2(t.x + e.x, t.y + e.y);
    }

    // Phase C: rescan with carry init, write fp16 hi + scaled lo
    uint32_t* hi = (uint32_t*)g_Ahi;
    uint32_t* lo = (uint32_t*)g_Alo;
    x = carry;
    #pragma unroll 4
    for (int t = 0; t < T_CHUNK; t++) {
        float2 v = g_Bu[base + (size_t)t * P_STATE];
        x = make_float2(fmaf(a.x, x.x, fmaf(-a.y, x.y, v.x)),
                        fmaf(a.x, x.y, fmaf(a.y, x.x, v.y)));
        __half2 h = __floats2half2_rn(x.x, x.y);
        float2 hf = __half22float2(h);
        __half2 l2 = __floats2half2_rn((x.x - hf.x) * 2048.0f, (x.y - hf.y) * 2048.0f);
        const size_t idx = base + (size_t)t * P_STATE;     // == l*256 + p
        hi[idx] = *(uint32_t*)&h;
        lo[idx] = *(uint32_t*)&l2;
    }
}

// ---------------------------------------------------------------------------
extern "C" void kernel_launch(void* const* d_in, const int* in_sizes, int n_in,
                              void* d_out, int out_size) {
    const float* u     = (const float*)d_in[0];
    const float* lr    = (const float*)d_in[1];
    const float* li    = (const float*)d_in[2];
    const float* b     = (const float*)d_in[3];
    const float* c     = (const float*)d_in[4];
    const float* d     = (const float*)d_in[5];
    const float* delta = (const float*)d_in[6];
    float* out = (float*)d_out;

    float2* bu2;       cudaGetSymbolAddress((void**)&bu2, g_Bu);
    __half* ahi;       cudaGetSymbolAddress((void**)&ahi, g_Ahi);
    __half* alo;       cudaGetSymbolAddress((void**)&alo, g_Alo);
    __half* w1hi;      cudaGetSymbolAddress((void**)&w1hi, g_W1hi);
    __half* w1lo;      cudaGetSymbolAddress((void**)&w1lo, g_W1lo);
    __half* w2hi;      cudaGetSymbolAddress((void**)&w2hi, g_W2hi);
    __half* w2lo;      cudaGetSymbolAddress((void**)&w2lo, g_W2lo);
    float* buf = (float*)bu2;

    cudaFuncSetAttribute(gemm_fp16<false>, cudaFuncAttributeMaxDynamicSharedMemorySize, SMEMB);
    cudaFuncSetAttribute(gemm_fp16<true>,  cudaFuncAttributeMaxDynamicSharedMemorySize, SMEMB);

    const int N4 = L_SEQ * N2 / 4;

    prep_params<<<1, P_STATE>>>(lr, li, delta);
    zero_flags<<<1, C_CHUNKS>>>();
    prep_weights<<<P_STATE, H_FEAT>>>(b, c);
    convert_split<<<2048, 256>>>((const float4*)u, (uint2*)ahi, (uint2*)alo, N4);
    gemm_fp16<false><<<dim3(N2 / BN, L_SEQ / BM), 256, SMEMB>>>(
        ahi, alo, w1hi, w1lo, buf, nullptr, nullptr);
    scan_fused<<<C_CHUNKS, P_STATE>>>();
    gemm_fp16<true><<<dim3(H_FEAT / BN, L_SEQ / BM), 256, SMEMB>>>(
        ahi, alo, w2hi, w2lo, out, u, d);
}

// round 10
// speedup vs baseline: 1.6051x; 1.6051x over previous
#include <cuda_runtime.h>
#include <cuda_fp16.h>
#include <cstdint>

// ---------------------------------------------------------------------------
// S5 SSM: ys = 2*Re( scan(Lam_bar, B_bar@u) @ C^T ) + d*u
// GEMMs: mma.sync fp16 hi/lo split, 3 terms:
//    main AhBh -> f32 accum, cross AhBl'+Al'Bh -> shared f16 accum (lo pre-
//    scaled by 2048; epilogue adds accC/2048)
// Scan: R4-style 3-kernel (local scan, Kogge-Stone carry, correct+split)
// (R10: third submission of this experiment; R6/R9 hit GB300 broker
//  infra failures before any compile/run evidence was produced)
// ---------------------------------------------------------------------------

#define L_SEQ   32768
#define H_FEAT  512
#define P_STATE 256
#define N2      512
#define C_CHUNKS 512
#define T_CHUNK  64
#define SQ_POW   6
#define INV2048 (1.0f / 2048.0f)

#define BM 128
#define BN 128
#define NCH 16             // 512 / 32
#define ROWB 80            // padded smem row bytes (64B data + 16B pad)
#define OP_BYTES (128 * ROWB)          // 10240 per operand tile
#define STG_BYTES (4 * OP_BYTES)       // Ah, Al, Bh, Bl
#define NSTAGE 3
#define SMEMB (NSTAGE * STG_BYTES)     // 122880

// Scratch (static __device__; no cudaMalloc allowed)
__device__ float2 g_Bu[L_SEQ * P_STATE];               // 64 MB
__device__ __half g_Ahi[L_SEQ * N2];                   // 32 MB
__device__ __half g_Alo[L_SEQ * N2];                   // 32 MB (scaled x2048)
__device__ __half g_W1hi[N2 * H_FEAT], g_W1lo[N2 * H_FEAT];
__device__ __half g_W2hi[H_FEAT * N2], g_W2lo[H_FEAT * N2];
__device__ float2 g_a[P_STATE];
__device__ float2 g_aT[P_STATE];
__device__ float2 g_Bscale[P_STATE];
__device__ float2 g_end[C_CHUNKS * P_STATE];
__device__ float2 g_carry[C_CHUNKS * P_STATE];

__device__ __forceinline__ float2 cmul(float2 a, float2 b) {
    return make_float2(a.x * b.x - a.y * b.y, a.x * b.y + a.y * b.x);
}

__device__ __forceinline__ uint32_t smem_u32(const void* p) {
    uint32_t a;
    asm("{ .reg .u64 t; cvta.to.shared.u64 t, %1; cvt.u32.u64 %0, t; }"
        : "=r"(a) : "l"(p));
    return a;
}
__device__ __forceinline__ void cp16(uint32_t dst, const void* src) {
    asm volatile("cp.async.cg.shared.global [%0], [%1], 16;" :: "r"(dst), "l"(src));
}
__device__ __forceinline__ void ldsm4(uint32_t* r, uint32_t addr) {
    asm volatile("ldmatrix.sync.aligned.m8n8.x4.shared.b16 {%0,%1,%2,%3}, [%4];"
                 : "=r"(r[0]), "=r"(r[1]), "=r"(r[2]), "=r"(r[3]) : "r"(addr));
}
// f32-accum fp16 MMA
__device__ __forceinline__ void mma_f32(float* d, const uint32_t* a,
                                        uint32_t b0, uint32_t b1) {
    asm volatile(
        "mma.sync.aligned.m16n8k16.row.col.f32.f16.f16.f32 "
        "{%0,%1,%2,%3}, {%4,%5,%6,%7}, {%8,%9}, {%0,%1,%2,%3};"
        : "+f"(d[0]), "+f"(d[1]), "+f"(d[2]), "+f"(d[3])
        : "r"(a[0]), "r"(a[1]), "r"(a[2]), "r"(a[3]), "r"(b0), "r"(b1));
}
// f16-accum fp16 MMA
__device__ __forceinline__ void mma_f16(uint32_t* d, const uint32_t* a,
                                        uint32_t b0, uint32_t b1) {
    asm volatile(
        "mma.sync.aligned.m16n8k16.row.col.f16.f16.f16.f16 "
        "{%0,%1}, {%2,%3,%4,%5}, {%6,%7}, {%0,%1};"
        : "+r"(d[0]), "+r"(d[1])
        : "r"(a[0]), "r"(a[1]), "r"(a[2]), "r"(a[3]), "r"(b0), "r"(b1));
}

// ---------------------------------------------------------------------------
__global__ void prep_params(const float* __restrict__ lr,
                            const float* __restrict__ li,
                            const float* __restrict__ delta) {
    int p = threadIdx.x;
    float step = expf(delta[p]);
    float hs = 0.5f * step;
    float dr = 1.0f - hs * lr[p];
    float di = -hs * li[p];
    float inv = 1.0f / (dr * dr + di * di);
    float2 BL = make_float2(dr * inv, -di * inv);
    float2 num = make_float2(1.0f + hs * lr[p], hs * li[p]);
    float2 a = cmul(BL, num);
    g_a[p] = a;
    g_Bscale[p] = make_float2(BL.x * step, BL.y * step);
    float2 t = a;
    #pragma unroll
    for (int i = 0; i < SQ_POW; i++) t = cmul(t, t);
    g_aT[p] = t;
}

__device__ __forceinline__ void store_split(__half* hi, __half* lo,
                                            int idx, float v) {
    __half h = __float2half_rn(v);
    hi[idx] = h;
    lo[idx] = __float2half_rn((v - __half2float(h)) * 2048.0f);
}

__global__ void prep_weights(const float* __restrict__ b,
                             const float* __restrict__ c) {
    int p = blockIdx.x;        // 0..255
    int h = threadIdx.x;       // 0..511
    float2 bs = g_Bscale[p];
    float br = b[(p * H_FEAT + h) * 2 + 0];
    float bi = b[(p * H_FEAT + h) * 2 + 1];
    store_split(g_W1hi, g_W1lo, (2 * p) * H_FEAT + h, bs.x * br - bs.y * bi);
    store_split(g_W1hi, g_W1lo, (2 * p + 1) * H_FEAT + h, bs.x * bi + bs.y * br);
    store_split(g_W2hi, g_W2lo, h * N2 + 2 * p,      2.0f * c[(h * P_STATE + p) * 2 + 0]);
    store_split(g_W2hi, g_W2lo, h * N2 + 2 * p + 1, -2.0f * c[(h * P_STATE + p) * 2 + 1]);
}

// fp32 -> fp16 hi + scaled-lo split (grid-stride, float4)
__global__ void convert_split(const float4* __restrict__ src,
                              uint2* __restrict__ hi, uint2* __restrict__ lo, int n4) {
    int stride = gridDim.x * blockDim.x;
    for (int i = blockIdx.x * blockDim.x + threadIdx.x; i < n4; i += stride) {
        float4 v = src[i];
        __half2 h0 = __floats2half2_rn(v.x, v.y);
        __half2 h1 = __floats2half2_rn(v.z, v.w);
        float2 f0 = __half22float2(h0);
        float2 f1 = __half22float2(h1);
        __half2 l0 = __floats2half2_rn((v.x - f0.x) * 2048.0f, (v.y - f0.y) * 2048.0f);
        __half2 l1 = __floats2half2_rn((v.z - f1.x) * 2048.0f, (v.w - f1.y) * 2048.0f);
        hi[i] = make_uint2(*(uint32_t*)&h0, *(uint32_t*)&h1);
        lo[i] = make_uint2(*(uint32_t*)&l0, *(uint32_t*)&l1);
    }
}

// ---------------------------------------------------------------------------
// fp16 split GEMM: C[M,512] = (Ah+Al/2048)[M,K] x (Bh+Bl/2048)[N,K]^T
// block 128x128, 256 thr, warp 32x64; main f32-acc, cross f16-acc
// ---------------------------------------------------------------------------
template <bool EPI>
__global__ void __launch_bounds__(256, 1)
gemm_fp16(const __half* __restrict__ Ahi, const __half* __restrict__ Alo,
          const __half* __restrict__ Bhi, const __half* __restrict__ Blo,
          float* __restrict__ Cout, const float* __restrict__ U,
          const float* __restrict__ D) {
    extern __shared__ char smem[];
    const uint32_t sb = smem_u32(smem);
    const int tid = threadIdx.x;
    const int wid = tid >> 5, lane = tid & 31;
    const int warpM = wid & 3, warpN = wid >> 2;       // 4x2 warp grid
    const int bm = blockIdx.y * BM;
    const int bn = blockIdx.x * BN;

    const char* bases[4] = {
        (const char*)Ahi + (size_t)bm * 1024,
        (const char*)Alo + (size_t)bm * 1024,
        (const char*)Bhi + (size_t)bn * 1024,
        (const char*)Blo + (size_t)bn * 1024 };

    auto load_chunk = [&](int kt, int st) {
        const uint32_t base = sb + st * STG_BYTES;
        const int kb = kt * 64;                        // byte offset into row
        const int s = tid & 3;
        #pragma unroll
        for (int j = 0; j < 8; j++) {
            const int op = j >> 1;
            const int r = (tid >> 2) + ((j & 1) << 6);
            cp16(base + op * OP_BYTES + r * ROWB + s * 16,
                 bases[op] + (size_t)r * 1024 + kb + s * 16);
        }
        asm volatile("cp.async.commit_group;");
    };

    load_chunk(0, 0);
    load_chunk(1, 1);

    float acc[2][8][4];
    uint32_t accC[2][8][2];
    #pragma unroll
    for (int im = 0; im < 2; im++)
        #pragma unroll
        for (int in = 0; in < 8; in++) {
            #pragma unroll
            for (int q = 0; q < 4; q++) acc[im][in][q] = 0.0f;
            accC[im][in][0] = 0u; accC[im][in][1] = 0u;
        }

    const uint32_t a_lo = (lane & 15) * ROWB + (lane >> 4) * 16;
    const uint32_t b_lo = ((lane & 7) + ((lane >> 4) << 3)) * ROWB +
                          ((lane >> 3) & 1) * 16;

    for (int kt = 0; kt < NCH; kt++) {
        const int st = kt % NSTAGE;
        if (kt == NCH - 1) asm volatile("cp.async.wait_group 0;");
        else               asm volatile("cp.async.wait_group 1;");
        __syncthreads();
        if (kt + 2 < NCH) load_chunk(kt + 2, (kt + 2) % NSTAGE);

        const uint32_t sg = sb + st * STG_BYTES;
        #pragma unroll
        for (int ks = 0; ks < 2; ks++) {
            const uint32_t ksb = ks * 32;
            uint32_t ah[2][4], al[2][4], bh[4][4], bl[4][4];
            #pragma unroll
            for (int im = 0; im < 2; im++) {
                const uint32_t ao = (warpM * 32 + im * 16) * ROWB + a_lo + ksb;
                ldsm4(ah[im], sg + ao);
                ldsm4(al[im], sg + OP_BYTES + ao);
            }
            #pragma unroll
            for (int ip = 0; ip < 4; ip++) {
                const uint32_t bo = (warpN * 64 + ip * 16) * ROWB + b_lo + ksb;
                ldsm4(bh[ip], sg + 2 * OP_BYTES + bo);
                ldsm4(bl[ip], sg + 3 * OP_BYTES + bo);
            }
            // main term: f32 accum
            #pragma unroll
            for (int im = 0; im < 2; im++)
                #pragma unroll
                for (int ip = 0; ip < 4; ip++) {
                    mma_f32(acc[im][2 * ip],     ah[im], bh[ip][0], bh[ip][1]);
                    mma_f32(acc[im][2 * ip + 1], ah[im], bh[ip][2], bh[ip][3]);
                }
            // cross terms: shared f16 accum (both scaled by 2048)
            #pragma unroll
            for (int im = 0; im < 2; im++)
                #pragma unroll
                for (int ip = 0; ip < 4; ip++) {
                    mma_f16(accC[im][2 * ip],     ah[im], bl[ip][0], bl[ip][1]);
                    mma_f16(accC[im][2 * ip + 1], ah[im], bl[ip][2], bl[ip][3]);
                    mma_f16(accC[im][2 * ip],     al[im], bh[ip][0], bh[ip][1]);
                    mma_f16(accC[im][2 * ip + 1], al[im], bh[ip][2], bh[ip][3]);
                }
        }
    }

    #pragma unroll
    for (int im = 0; im < 2; im++) {
        const int row0 = bm + warpM * 32 + im * 16 + (lane >> 2);
        #pragma unroll
        for (int in = 0; in < 8; in++) {
            const int col = bn + warpN * 64 + in * 8 + (lane & 3) * 2;
            float2 c0 = __half22float2(*(__half2*)&accC[im][in][0]);
            float2 c1 = __half22float2(*(__half2*)&accC[im][in][1]);
            float2 v0 = make_float2(fmaf(c0.x, INV2048, acc[im][in][0]),
                                    fmaf(c0.y, INV2048, acc[im][in][1]));
            float2 v1 = make_float2(fmaf(c1.x, INV2048, acc[im][in][2]),
                                    fmaf(c1.y, INV2048, acc[im][in][3]));
            if constexpr (EPI) {
                float2 dv = *(const float2*)&D[col];
                float2 u0 = *(const float2*)&U[(size_t)row0 * H_FEAT + col];
                float2 u1 = *(const float2*)&U[(size_t)(row0 + 8) * H_FEAT + col];
                v0.x = fmaf(dv.x, u0.x, v0.x); v0.y = fmaf(dv.y, u0.y, v0.y);
                v1.x = fmaf(dv.x, u1.x, v1.x); v1.y = fmaf(dv.y, u1.y, v1.y);
            }
            *(float2*)&Cout[(size_t)row0 * H_FEAT + col] = v0;
            *(float2*)&Cout[(size_t)(row0 + 8) * H_FEAT + col] = v1;
        }
    }
}

// ---------------------------------------------------------------------------
// Chunked recurrence scan (R4 structure)
// ---------------------------------------------------------------------------
__global__ void __launch_bounds__(256) scan_kernel() {
    const int p = threadIdx.x;
    const int c = blockIdx.x;
    const float2 a = g_a[p];
    float2 x = make_float2(0.0f, 0.0f);
    size_t base = (size_t)c * T_CHUNK * P_STATE + p;
    #pragma unroll 8
    for (int t = 0; t < T_CHUNK; t++) {
        float2 v = g_Bu[base + (size_t)t * P_STATE];
        float xr = fmaf(a.x, x.x, fmaf(-a.y, x.y, v.x));
        float xi = fmaf(a.x, x.y, fmaf(a.y, x.x, v.y));
        x = make_float2(xr, xi);
        g_Bu[base + (size_t)t * P_STATE] = x;
    }
    g_end[c * P_STATE + p] = x;
}

__global__ void __launch_bounds__(C_CHUNKS) carry_kernel() {
    __shared__ float2 s[C_CHUNKS];
    const int p = blockIdx.x;
    const int c = threadIdx.x;
    const float2 aT = g_aT[p];
    s[c] = g_end[c * P_STATE + p];
    float2 m = aT;
    __syncthreads();
    for (int d = 1; d < C_CHUNKS; d <<= 1) {
        float2 other = make_float2(0.0f, 0.0f);
        if (c >= d) other = s[c - d];
        __syncthreads();
        if (c >= d) {
            float2 cur = s[c];
            s[c] = make_float2(cur.x + m.x * other.x - m.y * other.y,
                               cur.y + m.x * other.y + m.y * other.x);
        }
        m = cmul(m, m);
        __syncthreads();
    }
    float2 ci = make_float2(0.0f, 0.0f);
    if (c > 0) ci = s[c - 1];
    g_carry[c * P_STATE + p] = ci;
}

// Fused: x_global = x_local + a^{t+1}*carry, then fp16 hi + scaled-lo split
__global__ void __launch_bounds__(256) correct_convert_kernel() {
    const int p = threadIdx.x;
    const int c = blockIdx.x;
    const float2 a = g_a[p];
    float2 cc = cmul(a, g_carry[c * P_STATE + p]);   // zero for c==0
    const size_t base = (size_t)c * T_CHUNK * P_STATE + p;
    uint32_t* hi = (uint32_t*)g_Ahi;
    uint32_t* lo = (uint32_t*)g_Alo;
    #pragma unroll 4
    for (int t = 0; t < T_CHUNK; t++) {
        float2 v = g_Bu[base + (size_t)t * P_STATE];
        v.x += cc.x;
        v.y += cc.y;
        const size_t idx = base + (size_t)t * P_STATE;   // == l*256 + p
        __half2 h = __floats2half2_rn(v.x, v.y);
        float2 hf = __half22float2(h);
        __half2 l2 = __floats2half2_rn((v.x - hf.x) * 2048.0f, (v.y - hf.y) * 2048.0f);
        hi[idx] = *(uint32_t*)&h;
        lo[idx] = *(uint32_t*)&l2;
        cc = cmul(cc, a);
    }
}

// ---------------------------------------------------------------------------
extern "C" void kernel_launch(void* const* d_in, const int* in_sizes, int n_in,
                              void* d_out, int out_size) {
    const float* u     = (const float*)d_in[0];
    const float* lr    = (const float*)d_in[1];
    const float* li    = (const float*)d_in[2];
    const float* b     = (const float*)d_in[3];
    const float* c     = (const float*)d_in[4];
    const float* d     = (const float*)d_in[5];
    const float* delta = (const float*)d_in[6];
    float* out = (float*)d_out;

    float2* bu2;       cudaGetSymbolAddress((void**)&bu2, g_Bu);
    __half* ahi;       cudaGetSymbolAddress((void**)&ahi, g_Ahi);
    __half* alo;       cudaGetSymbolAddress((void**)&alo, g_Alo);
    __half* w1hi;      cudaGetSymbolAddress((void**)&w1hi, g_W1hi);
    __half* w1lo;      cudaGetSymbolAddress((void**)&w1lo, g_W1lo);
    __half* w2hi;      cudaGetSymbolAddress((void**)&w2hi, g_W2hi);
    __half* w2lo;      cudaGetSymbolAddress((void**)&w2lo, g_W2lo);
    float* buf = (float*)bu2;

    cudaFuncSetAttribute(gemm_fp16<false>, cudaFuncAttributeMaxDynamicSharedMemorySize, SMEMB);
    cudaFuncSetAttribute(gemm_fp16<true>,  cudaFuncAttributeMaxDynamicSharedMemorySize, SMEMB);

    const int N4 = L_SEQ * N2 / 4;

    prep_params<<<1, P_STATE>>>(lr, li, delta);
    prep_weights<<<P_STATE, H_FEAT>>>(b, c);
    convert_split<<<2048, 256>>>((const float4*)u, (uint2*)ahi, (uint2*)alo, N4);
    gemm_fp16<false><<<dim3(N2 / BN, L_SEQ / BM), 256, SMEMB>>>(
        ahi, alo, w1hi, w1lo, buf, nullptr, nullptr);
    scan_kernel<<<C_CHUNKS, P_STATE>>>();
    carry_kernel<<<P_STATE, C_CHUNKS>>>();
    correct_convert_kernel<<<C_CHUNKS, P_STATE>>>();
    gemm_fp16<true><<<dim3(H_FEAT / BN, L_SEQ / BM), 256, SMEMB>>>(
        ahi, alo, w2hi, w2lo, out, u, d);
}

// round 11
// speedup vs baseline: 2.0112x; 1.2531x over previous
#include <cuda_runtime.h>
#include <cuda_fp16.h>
#include <cstdint>

// ---------------------------------------------------------------------------
// S5 SSM: ys = 2*Re( scan(Lam_bar, B_bar@u) @ C^T ) + d*u
// GEMMs: mma.sync fp16 2-term split: A = Ah + Al/2048 (both fp16),
//        B = fp16(W) single-rounded; both terms f32-accum.
//        (R10 falsified the acc-type hypothesis: mma.sync is rate-bound at
//         ~3.6 cyc/HMMA/SM, so time ∝ HMMA count → 3 terms -> 2 terms.)
// Scan: R4-style 3-kernel (local scan, Kogge-Stone carry, correct+split)
// ---------------------------------------------------------------------------

#define L_SEQ   32768
#define H_FEAT  512
#define P_STATE 256
#define N2      512
#define C_CHUNKS 512
#define T_CHUNK  64
#define SQ_POW   6
#define INV2048 (1.0f / 2048.0f)

#define BM 128
#define BN 128
#define NCH 16             // 512 / 32
#define ROWB 80            // padded smem row bytes (64B data + 16B pad)
#define OP_BYTES (128 * ROWB)          // 10240 per operand tile
#define STG_BYTES (3 * OP_BYTES)       // Ah, Al, B
#define NSTAGE 3
#define SMEMB (NSTAGE * STG_BYTES)     // 92160

// Scratch (static __device__; no cudaMalloc allowed)
__device__ float2 g_Bu[L_SEQ * P_STATE];               // 64 MB
__device__ __half g_Ahi[L_SEQ * N2];                   // 32 MB
__device__ __half g_Alo[L_SEQ * N2];                   // 32 MB (scaled x2048)
__device__ __half g_W1h[N2 * H_FEAT];
__device__ __half g_W2h[H_FEAT * N2];
__device__ float2 g_a[P_STATE];
__device__ float2 g_aT[P_STATE];
__device__ float2 g_Bscale[P_STATE];
__device__ float2 g_end[C_CHUNKS * P_STATE];
__device__ float2 g_carry[C_CHUNKS * P_STATE];

__device__ __forceinline__ float2 cmul(float2 a, float2 b) {
    return make_float2(a.x * b.x - a.y * b.y, a.x * b.y + a.y * b.x);
}

__device__ __forceinline__ uint32_t smem_u32(const void* p) {
    uint32_t a;
    asm("{ .reg .u64 t; cvta.to.shared.u64 t, %1; cvt.u32.u64 %0, t; }"
        : "=r"(a) : "l"(p));
    return a;
}
__device__ __forceinline__ void cp16(uint32_t dst, const void* src) {
    asm volatile("cp.async.cg.shared.global [%0], [%1], 16;" :: "r"(dst), "l"(src));
}
__device__ __forceinline__ void ldsm4(uint32_t* r, uint32_t addr) {
    asm volatile("ldmatrix.sync.aligned.m8n8.x4.shared.b16 {%0,%1,%2,%3}, [%4];"
                 : "=r"(r[0]), "=r"(r[1]), "=r"(r[2]), "=r"(r[3]) : "r"(addr));
}
// f32-accum fp16 MMA
__device__ __forceinline__ void mma_f32(float* d, const uint32_t* a,
                                        uint32_t b0, uint32_t b1) {
    asm volatile(
        "mma.sync.aligned.m16n8k16.row.col.f32.f16.f16.f32 "
        "{%0,%1,%2,%3}, {%4,%5,%6,%7}, {%8,%9}, {%0,%1,%2,%3};"
        : "+f"(d[0]), "+f"(d[1]), "+f"(d[2]), "+f"(d[3])
        : "r"(a[0]), "r"(a[1]), "r"(a[2]), "r"(a[3]), "r"(b0), "r"(b1));
}

// ---------------------------------------------------------------------------
__global__ void prep_params(const float* __restrict__ lr,
                            const float* __restrict__ li,
                            const float* __restrict__ delta) {
    int p = threadIdx.x;
    float step = expf(delta[p]);
    float hs = 0.5f * step;
    float dr = 1.0f - hs * lr[p];
    float di = -hs * li[p];
    float inv = 1.0f / (dr * dr + di * di);
    float2 BL = make_float2(dr * inv, -di * inv);
    float2 num = make_float2(1.0f + hs * lr[p], hs * li[p]);
    float2 a = cmul(BL, num);
    g_a[p] = a;
    g_Bscale[p] = make_float2(BL.x * step, BL.y * step);
    float2 t = a;
    #pragma unroll
    for (int i = 0; i < SQ_POW; i++) t = cmul(t, t);
    g_aT[p] = t;
}

__global__ void prep_weights(const float* __restrict__ b,
                             const float* __restrict__ c) {
    int p = blockIdx.x;        // 0..255
    int h = threadIdx.x;       // 0..511
    float2 bs = g_Bscale[p];
    float br = b[(p * H_FEAT + h) * 2 + 0];
    float bi = b[(p * H_FEAT + h) * 2 + 1];
    // W1 as [n=2p|2p+1][k=h]  (mma B operand: [N][K], K contiguous)
    g_W1h[(2 * p) * H_FEAT + h]     = __float2half_rn(bs.x * br - bs.y * bi);
    g_W1h[(2 * p + 1) * H_FEAT + h] = __float2half_rn(bs.x * bi + bs.y * br);
    // W2 as [n=h][k=2p|2p+1]
    g_W2h[h * N2 + 2 * p]     = __float2half_rn( 2.0f * c[(h * P_STATE + p) * 2 + 0]);
    g_W2h[h * N2 + 2 * p + 1] = __float2half_rn(-2.0f * c[(h * P_STATE + p) * 2 + 1]);
}

// fp32 -> fp16 hi + scaled-lo split (grid-stride, float4)
__global__ void convert_split(const float4* __restrict__ src,
                              uint2* __restrict__ hi, uint2* __restrict__ lo, int n4) {
    int stride = gridDim.x * blockDim.x;
    for (int i = blockIdx.x * blockDim.x + threadIdx.x; i < n4; i += stride) {
        float4 v = src[i];
        __half2 h0 = __floats2half2_rn(v.x, v.y);
        __half2 h1 = __floats2half2_rn(v.z, v.w);
        float2 f0 = __half22float2(h0);
        float2 f1 = __half22float2(h1);
        __half2 l0 = __floats2half2_rn((v.x - f0.x) * 2048.0f, (v.y - f0.y) * 2048.0f);
        __half2 l1 = __floats2half2_rn((v.z - f1.x) * 2048.0f, (v.w - f1.y) * 2048.0f);
        hi[i] = make_uint2(*(uint32_t*)&h0, *(uint32_t*)&h1);
        lo[i] = make_uint2(*(uint32_t*)&l0, *(uint32_t*)&l1);
    }
}

// ---------------------------------------------------------------------------
// fp16 2-term GEMM: C[M,512] = (Ah+Al/2048)[M,K] x B[N,K]^T
// block 128x128, 256 thr, warp 32x64; both terms f32-acc
// ---------------------------------------------------------------------------
template <bool EPI>
__global__ void __launch_bounds__(256, 1)
gemm_fp16(const __half* __restrict__ Ahi, const __half* __restrict__ Alo,
          const __half* __restrict__ Bw,
          float* __restrict__ Cout, const float* __restrict__ U,
          const float* __restrict__ D) {
    extern __shared__ char smem[];
    const uint32_t sb = smem_u32(smem);
    const int tid = threadIdx.x;
    const int wid = tid >> 5, lane = tid & 31;
    const int warpM = wid & 3, warpN = wid >> 2;       // 4x2 warp grid
    const int bm = blockIdx.y * BM;
    const int bn = blockIdx.x * BN;

    const char* bases[3] = {
        (const char*)Ahi + (size_t)bm * 1024,
        (const char*)Alo + (size_t)bm * 1024,
        (const char*)Bw  + (size_t)bn * 1024 };

    auto load_chunk = [&](int kt, int st) {
        const uint32_t base = sb + st * STG_BYTES;
        const int kb = kt * 64;                        // byte offset into row
        const int s = tid & 3;
        #pragma unroll
        for (int j = 0; j < 6; j++) {
            const int op = j >> 1;
            const int r = (tid >> 2) + ((j & 1) << 6);
            cp16(base + op * OP_BYTES + r * ROWB + s * 16,
                 bases[op] + (size_t)r * 1024 + kb + s * 16);
        }
        asm volatile("cp.async.commit_group;");
    };

    load_chunk(0, 0);
    load_chunk(1, 1);

    float acc[2][8][4];
    float accL[2][8][4];
    #pragma unroll
    for (int im = 0; im < 2; im++)
        #pragma unroll
        for (int in = 0; in < 8; in++)
            #pragma unroll
            for (int q = 0; q < 4; q++) { acc[im][in][q] = 0.0f; accL[im][in][q] = 0.0f; }

    const uint32_t a_lo = (lane & 15) * ROWB + (lane >> 4) * 16;
    const uint32_t b_lo = ((lane & 7) + ((lane >> 4) << 3)) * ROWB +
                          ((lane >> 3) & 1) * 16;

    for (int kt = 0; kt < NCH; kt++) {
        const int st = kt % NSTAGE;
        if (kt == NCH - 1) asm volatile("cp.async.wait_group 0;");
        else               asm volatile("cp.async.wait_group 1;");
        __syncthreads();
        if (kt + 2 < NCH) load_chunk(kt + 2, (kt + 2) % NSTAGE);

        const uint32_t sg = sb + st * STG_BYTES;
        #pragma unroll
        for (int ks = 0; ks < 2; ks++) {
            const uint32_t ksb = ks * 32;
            uint32_t ah[2][4], al[2][4], bh[4][4];
            #pragma unroll
            for (int im = 0; im < 2; im++) {
                const uint32_t ao = (warpM * 32 + im * 16) * ROWB + a_lo + ksb;
                ldsm4(ah[im], sg + ao);
                ldsm4(al[im], sg + OP_BYTES + ao);
            }
            #pragma unroll
            for (int ip = 0; ip < 4; ip++) {
                const uint32_t bo = (warpN * 64 + ip * 16) * ROWB + b_lo + ksb;
                ldsm4(bh[ip], sg + 2 * OP_BYTES + bo);
            }
            // term 1: Ah x B -> acc
            #pragma unroll
            for (int im = 0; im < 2; im++)
                #pragma unroll
                for (int ip = 0; ip < 4; ip++) {
                    mma_f32(acc[im][2 * ip],     ah[im], bh[ip][0], bh[ip][1]);
                    mma_f32(acc[im][2 * ip + 1], ah[im], bh[ip][2], bh[ip][3]);
                }
            // term 2: Al x B -> accL (Al pre-scaled x2048)
            #pragma unroll
            for (int im = 0; im < 2; im++)
                #pragma unroll
                for (int ip = 0; ip < 4; ip++) {
                    mma_f32(accL[im][2 * ip],     al[im], bh[ip][0], bh[ip][1]);
                    mma_f32(accL[im][2 * ip + 1], al[im], bh[ip][2], bh[ip][3]);
                }
        }
    }

    #pragma unroll
    for (int im = 0; im < 2; im++) {
        const int row0 = bm + warpM * 32 + im * 16 + (lane >> 2);
        #pragma unroll
        for (int in = 0; in < 8; in++) {
            const int col = bn + warpN * 64 + in * 8 + (lane & 3) * 2;
            float2 v0 = make_float2(fmaf(accL[im][in][0], INV2048, acc[im][in][0]),
                                    fmaf(accL[im][in][1], INV2048, acc[im][in][1]));
            float2 v1 = make_float2(fmaf(accL[im][in][2], INV2048, acc[im][in][2]),
                                    fmaf(accL[im][in][3], INV2048, acc[im][in][3]));
            if constexpr (EPI) {
                float2 dv = *(const float2*)&D[col];
                float2 u0 = *(const float2*)&U[(size_t)row0 * H_FEAT + col];
                float2 u1 = *(const float2*)&U[(size_t)(row0 + 8) * H_FEAT + col];
                v0.x = fmaf(dv.x, u0.x, v0.x); v0.y = fmaf(dv.y, u0.y, v0.y);
                v1.x = fmaf(dv.x, u1.x, v1.x); v1.y = fmaf(dv.y, u1.y, v1.y);
            }
            *(float2*)&Cout[(size_t)row0 * H_FEAT + col] = v0;
            *(float2*)&Cout[(size_t)(row0 + 8) * H_FEAT + col] = v1;
        }
    }
}

// ---------------------------------------------------------------------------
// Chunked recurrence scan (R4 structure)
// ---------------------------------------------------------------------------
__global__ void __launch_bounds__(256) scan_kernel() {
    const int p = threadIdx.x;
    const int c = blockIdx.x;
    const float2 a = g_a[p];
    float2 x = make_float2(0.0f, 0.0f);
    size_t base = (size_t)c * T_CHUNK * P_STATE + p;
    #pragma unroll 8
    for (int t = 0; t < T_CHUNK; t++) {
        float2 v = g_Bu[base + (size_t)t * P_STATE];
        float xr = fmaf(a.x, x.x, fmaf(-a.y, x.y, v.x));
        float xi = fmaf(a.x, x.y, fmaf(a.y, x.x, v.y));
        x = make_float2(xr, xi);
        g_Bu[base + (size_t)t * P_STATE] = x;
    }
    g_end[c * P_STATE + p] = x;
}

__global__ void __launch_bounds__(C_CHUNKS) carry_kernel() {
    __shared__ float2 s[C_CHUNKS];
    const int p = blockIdx.x;
    const int c = threadIdx.x;
    const float2 aT = g_aT[p];
    s[c] = g_end[c * P_STATE + p];
    float2 m = aT;
    __syncthreads();
    for (int d = 1; d < C_CHUNKS; d <<= 1) {
        float2 other = make_float2(0.0f, 0.0f);
        if (c >= d) other = s[c - d];
        __syncthreads();
        if (c >= d) {
            float2 cur = s[c];
            s[c] = make_float2(cur.x + m.x * other.x - m.y * other.y,
                               cur.y + m.x * other.y + m.y * other.x);
        }
        m = cmul(m, m);
        __syncthreads();
    }
    float2 ci = make_float2(0.0f, 0.0f);
    if (c > 0) ci = s[c - 1];
    g_carry[c * P_STATE + p] = ci;
}

// Fused: x_global = x_local + a^{t+1}*carry, then fp16 hi + scaled-lo split
__global__ void __launch_bounds__(256) correct_convert_kernel() {
    const int p = threadIdx.x;
    const int c = blockIdx.x;
    const float2 a = g_a[p];
    float2 cc = cmul(a, g_carry[c * P_STATE + p]);   // zero for c==0
    const size_t base = (size_t)c * T_CHUNK * P_STATE + p;
    uint32_t* hi = (uint32_t*)g_Ahi;
    uint32_t* lo = (uint32_t*)g_Alo;
    #pragma unroll 4
    for (int t = 0; t < T_CHUNK; t++) {
        float2 v = g_Bu[base + (size_t)t * P_STATE];
        v.x += cc.x;
        v.y += cc.y;
        const size_t idx = base + (size_t)t * P_STATE;   // == l*256 + p
        __half2 h = __floats2half2_rn(v.x, v.y);
        float2 hf = __half22float2(h);
        __half2 l2 = __floats2half2_rn((v.x - hf.x) * 2048.0f, (v.y - hf.y) * 2048.0f);
        hi[idx] = *(uint32_t*)&h;
        lo[idx] = *(uint32_t*)&l2;
        cc = cmul(cc, a);
    }
}

// ---------------------------------------------------------------------------
extern "C" void kernel_launch(void* const* d_in, const int* in_sizes, int n_in,
                              void* d_out, int out_size) {
    const float* u     = (const float*)d_in[0];
    const float* lr    = (const float*)d_in[1];
    const float* li    = (const float*)d_in[2];
    const float* b     = (const float*)d_in[3];
    const float* c     = (const float*)d_in[4];
    const float* d     = (const float*)d_in[5];
    const float* delta = (const float*)d_in[6];
    float* out = (float*)d_out;

    float2* bu2;       cudaGetSymbolAddress((void**)&bu2, g_Bu);
    __half* ahi;       cudaGetSymbolAddress((void**)&ahi, g_Ahi);
    __half* alo;       cudaGetSymbolAddress((void**)&alo, g_Alo);
    __half* w1h;       cudaGetSymbolAddress((void**)&w1h, g_W1h);
    __half* w2h;       cudaGetSymbolAddress((void**)&w2h, g_W2h);
    float* buf = (float*)bu2;

    cudaFuncSetAttribute(gemm_fp16<false>, cudaFuncAttributeMaxDynamicSharedMemorySize, SMEMB);
    cudaFuncSetAttribute(gemm_fp16<true>,  cudaFuncAttributeMaxDynamicSharedMemorySize, SMEMB);

    const int N4 = L_SEQ * N2 / 4;

    prep_params<<<1, P_STATE>>>(lr, li, delta);
    prep_weights<<<P_STATE, H_FEAT>>>(b, c);
    convert_split<<<2048, 256>>>((const float4*)u, (uint2*)ahi, (uint2*)alo, N4);
    gemm_fp16<false><<<dim3(N2 / BN, L_SEQ / BM), 256, SMEMB>>>(
        ahi, alo, w1h, buf, nullptr, nullptr);
    scan_kernel<<<C_CHUNKS, P_STATE>>>();
    carry_kernel<<<P_STATE, C_CHUNKS>>>();
    correct_convert_kernel<<<C_CHUNKS, P_STATE>>>();
    gemm_fp16<true><<<dim3(H_FEAT / BN, L_SEQ / BM), 256, SMEMB>>>(
        ahi, alo, w2h, out, u, d);
}

// round 12
// speedup vs baseline: 3.4409x; 1.7109x over previous
#include <cuda_runtime.h>
#include <cuda_fp16.h>
#include <cstdint>

// ---------------------------------------------------------------------------
// S5 SSM: ys = 2*Re( scan(Lam_bar, B_bar@u) @ C^T ) + d*u
// R12: pure single-rounded fp16 GEMMs (time ∝ HMMA count; R11 measured one
//      2^-11 rounding source = 1.37e-4 rel; four sources ≈ 2.7e-4 < 1e-3).
// Scan: ends-only -> Kogge-Stone carry -> rescan-with-carry writing fp16.
// ---------------------------------------------------------------------------

#define L_SEQ   32768
#define H_FEAT  512
#define P_STATE 256
#define N2      512
#define C_CHUNKS 512
#define T_CHUNK  64
#define SQ_POW   6

#define BM 128
#define BN 128
#define NCH 16             // 512 / 32
#define ROWB 80            // padded smem row bytes (64B data + 16B pad)
#define OP_BYTES (128 * ROWB)          // 10240 per operand tile
#define STG_BYTES (2 * OP_BYTES)       // A, B
#define NSTAGE 3
#define SMEMB (NSTAGE * STG_BYTES)     // 61440

// Scratch (static __device__; no cudaMalloc allowed)
__device__ float2 g_Bu[L_SEQ * P_STATE];               // 64 MB
__device__ __half g_Ah[L_SEQ * N2];                    // 32 MB (u, then xs)
__device__ __half g_W1h[N2 * H_FEAT];
__device__ __half g_W2h[H_FEAT * N2];
__device__ float2 g_a[P_STATE];
__device__ float2 g_aT[P_STATE];
__device__ float2 g_Bscale[P_STATE];
__device__ float2 g_end[C_CHUNKS * P_STATE];
__device__ float2 g_carry[C_CHUNKS * P_STATE];

__device__ __forceinline__ float2 cmul(float2 a, float2 b) {
    return make_float2(a.x * b.x - a.y * b.y, a.x * b.y + a.y * b.x);
}

__device__ __forceinline__ uint32_t smem_u32(const void* p) {
    uint32_t a;
    asm("{ .reg .u64 t; cvta.to.shared.u64 t, %1; cvt.u32.u64 %0, t; }"
        : "=r"(a) : "l"(p));
    return a;
}
__device__ __forceinline__ void cp16(uint32_t dst, const void* src) {
    asm volatile("cp.async.cg.shared.global [%0], [%1], 16;" :: "r"(dst), "l"(src));
}
__device__ __forceinline__ void ldsm4(uint32_t* r, uint32_t addr) {
    asm volatile("ldmatrix.sync.aligned.m8n8.x4.shared.b16 {%0,%1,%2,%3}, [%4];"
                 : "=r"(r[0]), "=r"(r[1]), "=r"(r[2]), "=r"(r[3]) : "r"(addr));
}
__device__ __forceinline__ void mma_f32(float* d, const uint32_t* a,
                                        uint32_t b0, uint32_t b1) {
    asm volatile(
        "mma.sync.aligned.m16n8k16.row.col.f32.f16.f16.f32 "
        "{%0,%1,%2,%3}, {%4,%5,%6,%7}, {%8,%9}, {%0,%1,%2,%3};"
        : "+f"(d[0]), "+f"(d[1]), "+f"(d[2]), "+f"(d[3])
        : "r"(a[0]), "r"(a[1]), "r"(a[2]), "r"(a[3]), "r"(b0), "r"(b1));
}

// ---------------------------------------------------------------------------
__global__ void prep_params(const float* __restrict__ lr,
                            const float* __restrict__ li,
                            const float* __restrict__ delta) {
    int p = threadIdx.x;
    float step = expf(delta[p]);
    float hs = 0.5f * step;
    float dr = 1.0f - hs * lr[p];
    float di = -hs * li[p];
    float inv = 1.0f / (dr * dr + di * di);
    float2 BL = make_float2(dr * inv, -di * inv);
    float2 num = make_float2(1.0f + hs * lr[p], hs * li[p]);
    float2 a = cmul(BL, num);
    g_a[p] = a;
    g_Bscale[p] = make_float2(BL.x * step, BL.y * step);
    float2 t = a;
    #pragma unroll
    for (int i = 0; i < SQ_POW; i++) t = cmul(t, t);
    g_aT[p] = t;
}

__global__ void prep_weights(const float* __restrict__ b,
                             const float* __restrict__ c) {
    int p = blockIdx.x;        // 0..255
    int h = threadIdx.x;       // 0..511
    float2 bs = g_Bscale[p];
    float br = b[(p * H_FEAT + h) * 2 + 0];
    float bi = b[(p * H_FEAT + h) * 2 + 1];
    // W1 as [n=2p|2p+1][k=h]  (mma B operand: [N][K], K contiguous)
    g_W1h[(2 * p) * H_FEAT + h]     = __float2half_rn(bs.x * br - bs.y * bi);
    g_W1h[(2 * p + 1) * H_FEAT + h] = __float2half_rn(bs.x * bi + bs.y * br);
    // W2 as [n=h][k=2p|2p+1]
    g_W2h[h * N2 + 2 * p]     = __float2half_rn( 2.0f * c[(h * P_STATE + p) * 2 + 0]);
    g_W2h[h * N2 + 2 * p + 1] = __float2half_rn(-2.0f * c[(h * P_STATE + p) * 2 + 1]);
}

// fp32 -> fp16 (grid-stride, float4 -> uint2)
__global__ void convert_half(const float4* __restrict__ src,
                             uint2* __restrict__ dst, int n4) {
    int stride = gridDim.x * blockDim.x;
    for (int i = blockIdx.x * blockDim.x + threadIdx.x; i < n4; i += stride) {
        float4 v = src[i];
        __half2 h0 = __floats2half2_rn(v.x, v.y);
        __half2 h1 = __floats2half2_rn(v.z, v.w);
        dst[i] = make_uint2(*(uint32_t*)&h0, *(uint32_t*)&h1);
    }
}

// ---------------------------------------------------------------------------
// fp16 GEMM: C[M,512] = A[M,K] x B[N,K]^T (single-rounded fp16, f32 accum)
// block 128x128, 256 thr, warp 32x64, K-chunks 32, 3-stage cp.async
// ---------------------------------------------------------------------------
template <bool EPI>
__global__ void __launch_bounds__(256, 1)
gemm_fp16(const __half* __restrict__ Ah, const __half* __restrict__ Bw,
          float* __restrict__ Cout, const float* __restrict__ U,
          const float* __restrict__ D) {
    extern __shared__ char smem[];
    const uint32_t sb = smem_u32(smem);
    const int tid = threadIdx.x;
    const int wid = tid >> 5, lane = tid & 31;
    const int warpM = wid & 3, warpN = wid >> 2;       // 4x2 warp grid
    const int bm = blockIdx.y * BM;
    const int bn = blockIdx.x * BN;

    const char* baseA = (const char*)Ah + (size_t)bm * 1024;
    const char* baseB = (const char*)Bw + (size_t)bn * 1024;

    auto load_chunk = [&](int kt, int st) {
        const uint32_t base = sb + st * STG_BYTES;
        const int kb = kt * 64;                        // byte offset into row
        const int s = tid & 3;
        #pragma unroll
        for (int j = 0; j < 4; j++) {
            const int op = j >> 1;
            const int r = (tid >> 2) + ((j & 1) << 6);
            cp16(base + op * OP_BYTES + r * ROWB + s * 16,
                 (op ? baseB : baseA) + (size_t)r * 1024 + kb + s * 16);
        }
        asm volatile("cp.async.commit_group;");
    };

    load_chunk(0, 0);
    load_chunk(1, 1);

    float acc[2][8][4];
    #pragma unroll
    for (int im = 0; im < 2; im++)
        #pragma unroll
        for (int in = 0; in < 8; in++)
            #pragma unroll
            for (int q = 0; q < 4; q++) acc[im][in][q] = 0.0f;

    const uint32_t a_lo = (lane & 15) * ROWB + (lane >> 4) * 16;
    const uint32_t b_lo = ((lane & 7) + ((lane >> 4) << 3)) * ROWB +
                          ((lane >> 3) & 1) * 16;

    for (int kt = 0; kt < NCH; kt++) {
        const int st = kt % NSTAGE;
        if (kt == NCH - 1) asm volatile("cp.async.wait_group 0;");
        else               asm volatile("cp.async.wait_group 1;");
        __syncthreads();
        if (kt + 2 < NCH) load_chunk(kt + 2, (kt + 2) % NSTAGE);

        const uint32_t sg = sb + st * STG_BYTES;
        #pragma unroll
        for (int ks = 0; ks < 2; ks++) {
            const uint32_t ksb = ks * 32;
            uint32_t ah[2][4], bh[4][4];
            #pragma unroll
            for (int im = 0; im < 2; im++) {
                const uint32_t ao = (warpM * 32 + im * 16) * ROWB + a_lo + ksb;
                ldsm4(ah[im], sg + ao);
            }
            #pragma unroll
            for (int ip = 0; ip < 4; ip++) {
                const uint32_t bo = (warpN * 64 + ip * 16) * ROWB + b_lo + ksb;
                ldsm4(bh[ip], sg + OP_BYTES + bo);
            }
            #pragma unroll
            for (int im = 0; im < 2; im++)
                #pragma unroll
                for (int ip = 0; ip < 4; ip++) {
                    mma_f32(acc[im][2 * ip],     ah[im], bh[ip][0], bh[ip][1]);
                    mma_f32(acc[im][2 * ip + 1], ah[im], bh[ip][2], bh[ip][3]);
                }
        }
    }

    #pragma unroll
    for (int im = 0; im < 2; im++) {
        const int row0 = bm + warpM * 32 + im * 16 + (lane >> 2);
        #pragma unroll
        for (int in = 0; in < 8; in++) {
            const int col = bn + warpN * 64 + in * 8 + (lane & 3) * 2;
            float2 v0 = make_float2(acc[im][in][0], acc[im][in][1]);
            float2 v1 = make_float2(acc[im][in][2], acc[im][in][3]);
            if constexpr (EPI) {
                float2 dv = *(const float2*)&D[col];
                float2 u0 = *(const float2*)&U[(size_t)row0 * H_FEAT + col];
                float2 u1 = *(const float2*)&U[(size_t)(row0 + 8) * H_FEAT + col];
                v0.x = fmaf(dv.x, u0.x, v0.x); v0.y = fmaf(dv.y, u0.y, v0.y);
                v1.x = fmaf(dv.x, u1.x, v1.x); v1.y = fmaf(dv.y, u1.y, v1.y);
            }
            *(float2*)&Cout[(size_t)row0 * H_FEAT + col] = v0;
            *(float2*)&Cout[(size_t)(row0 + 8) * H_FEAT + col] = v1;
        }
    }
}

// ---------------------------------------------------------------------------
// Scan stage 1: per-chunk end states only (no writeback of locals)
// ---------------------------------------------------------------------------
__global__ void __launch_bounds__(256) ends_kernel() {
    const int p = threadIdx.x;
    const int c = blockIdx.x;
    const float2 a = g_a[p];
    float2 x = make_float2(0.0f, 0.0f);
    size_t base = (size_t)c * T_CHUNK * P_STATE + p;
    #pragma unroll 8
    for (int t = 0; t < T_CHUNK; t++) {
        float2 v = g_Bu[base + (size_t)t * P_STATE];
        float xr = fmaf(a.x, x.x, fmaf(-a.y, x.y, v.x));
        float xi = fmaf(a.x, x.y, fmaf(a.y, x.x, v.y));
        x = make_float2(xr, xi);
    }
    g_end[c * P_STATE + p] = x;
}

// Stage 2: Kogge-Stone inclusive scan of ends; g_carry[c] = state entering c
__global__ void __launch_bounds__(C_CHUNKS) carry_kernel() {
    __shared__ float2 s[C_CHUNKS];
    const int p = blockIdx.x;
    const int c = threadIdx.x;
    const float2 aT = g_aT[p];
    s[c] = g_end[c * P_STATE + p];
    float2 m = aT;
    __syncthreads();
    for (int d = 1; d < C_CHUNKS; d <<= 1) {
        float2 other = make_float2(0.0f, 0.0f);
        if (c >= d) other = s[c - d];
        __syncthreads();
        if (c >= d) {
            float2 cur = s[c];
            s[c] = make_float2(cur.x + m.x * other.x - m.y * other.y,
                               cur.y + m.x * other.y + m.y * other.x);
        }
        m = cmul(m, m);
        __syncthreads();
    }
    float2 ci = make_float2(0.0f, 0.0f);
    if (c > 0) ci = s[c - 1];
    g_carry[c * P_STATE + p] = ci;
}

// Stage 3: rescan with carry init; write fp16 states directly
__global__ void __launch_bounds__(256) rescan_convert_kernel() {
    const int p = threadIdx.x;
    const int c = blockIdx.x;
    const float2 a = g_a[p];
    float2 x = g_carry[c * P_STATE + p];             // state entering chunk c
    const size_t base = (size_t)c * T_CHUNK * P_STATE + p;
    uint32_t* hi = (uint32_t*)g_Ah;
    #pragma unroll 4
    for (int t = 0; t < T_CHUNK; t++) {
        float2 v = g_Bu[base + (size_t)t * P_STATE];
        float xr = fmaf(a.x, x.x, fmaf(-a.y, x.y, v.x));
        float xi = fmaf(a.x, x.y, fmaf(a.y, x.x, v.y));
        x = make_float2(xr, xi);
        __half2 h = __floats2half2_rn(x.x, x.y);
        hi[base + (size_t)t * P_STATE] = *(uint32_t*)&h;   // idx == l*256 + p
    }
}

// ---------------------------------------------------------------------------
extern "C" void kernel_launch(void* const* d_in, const int* in_sizes, int n_in,
                              void* d_out, int out_size) {
    const float* u     = (const float*)d_in[0];
    const float* lr    = (const float*)d_in[1];
    const float* li    = (const float*)d_in[2];
    const float* b     = (const float*)d_in[3];
    const float* c     = (const float*)d_in[4];
    const float* d     = (const float*)d_in[5];
    const float* delta = (const float*)d_in[6];
    float* out = (float*)d_out;

    float2* bu2;       cudaGetSymbolAddress((void**)&bu2, g_Bu);
    __half* ah;        cudaGetSymbolAddress((void**)&ah, g_Ah);
    __half* w1h;       cudaGetSymbolAddress((void**)&w1h, g_W1h);
    __half* w2h;       cudaGetSymbolAddress((void**)&w2h, g_W2h);
    float* buf = (float*)bu2;

    cudaFuncSetAttribute(gemm_fp16<false>, cudaFuncAttributeMaxDynamicSharedMemorySize, SMEMB);
    cudaFuncSetAttribute(gemm_fp16<true>,  cudaFuncAttributeMaxDynamicSharedMemorySize, SMEMB);

    const int N4 = L_SEQ * N2 / 4;

    prep_params<<<1, P_STATE>>>(lr, li, delta);
    prep_weights<<<P_STATE, H_FEAT>>>(b, c);
    convert_half<<<2048, 256>>>((const float4*)u, (uint2*)ah, N4);
    gemm_fp16<false><<<dim3(N2 / BN, L_SEQ / BM), 256, SMEMB>>>(
        ah, w1h, buf, nullptr, nullptr);
    ends_kernel<<<C_CHUNKS, P_STATE>>>();
    carry_kernel<<<P_STATE, C_CHUNKS>>>();
    rescan_convert_kernel<<<C_CHUNKS, P_STATE>>>();
    gemm_fp16<true><<<dim3(H_FEAT / BN, L_SEQ / BM), 256, SMEMB>>>(
        ah, w2h, out, u, d);
}

// round 13
// speedup vs baseline: 3.8462x; 1.1178x over previous
#include <cuda_runtime.h>
#include <cuda_fp16.h>
#include <cstdint>

// ---------------------------------------------------------------------------
// S5 SSM: ys = 2*Re( scan(Lam_bar, B_bar@u) @ C^T ) + d*u
// R13: Bu intermediate stored fp16 (GEMM1 epilogue emits __half2; scan passes
//      read half the bytes). GEMM inner loop identical to R12 (63.8us each,
//      rate-bound at ~2.6 cyc/HMMA/SM).
// Scan: ends-only -> Kogge-Stone carry -> rescan-with-carry writing fp16.
// ---------------------------------------------------------------------------

#define L_SEQ   32768
#define H_FEAT  512
#define P_STATE 256
#define N2      512
#define C_CHUNKS 512
#define T_CHUNK  64
#define SQ_POW   6

#define BM 128
#define BN 128
#define NCH 16             // 512 / 32
#define ROWB 80            // padded smem row bytes (64B data + 16B pad)
#define OP_BYTES (128 * ROWB)          // 10240 per operand tile
#define STG_BYTES (2 * OP_BYTES)       // A, B
#define NSTAGE 3
#define SMEMB (NSTAGE * STG_BYTES)     // 61440

// Scratch (static __device__; no cudaMalloc allowed)
__device__ uint32_t g_BuH[L_SEQ * P_STATE];            // 32 MB, half2 (re,im)
__device__ __half g_Ah[L_SEQ * N2];                    // 32 MB (u, then xs)
__device__ __half g_W1h[N2 * H_FEAT];
__device__ __half g_W2h[H_FEAT * N2];
__device__ float2 g_a[P_STATE];
__device__ float2 g_aT[P_STATE];
__device__ float2 g_Bscale[P_STATE];
__device__ float2 g_end[C_CHUNKS * P_STATE];
__device__ float2 g_carry[C_CHUNKS * P_STATE];

__device__ __forceinline__ float2 cmul(float2 a, float2 b) {
    return make_float2(a.x * b.x - a.y * b.y, a.x * b.y + a.y * b.x);
}

__device__ __forceinline__ uint32_t smem_u32(const void* p) {
    uint32_t a;
    asm("{ .reg .u64 t; cvta.to.shared.u64 t, %1; cvt.u32.u64 %0, t; }"
        : "=r"(a) : "l"(p));
    return a;
}
__device__ __forceinline__ void cp16(uint32_t dst, const void* src) {
    asm volatile("cp.async.cg.shared.global [%0], [%1], 16;" :: "r"(dst), "l"(src));
}
__device__ __forceinline__ void ldsm4(uint32_t* r, uint32_t addr) {
    asm volatile("ldmatrix.sync.aligned.m8n8.x4.shared.b16 {%0,%1,%2,%3}, [%4];"
                 : "=r"(r[0]), "=r"(r[1]), "=r"(r[2]), "=r"(r[3]) : "r"(addr));
}
__device__ __forceinline__ void mma_f32(float* d, const uint32_t* a,
                                        uint32_t b0, uint32_t b1) {
    asm volatile(
        "mma.sync.aligned.m16n8k16.row.col.f32.f16.f16.f32 "
        "{%0,%1,%2,%3}, {%4,%5,%6,%7}, {%8,%9}, {%0,%1,%2,%3};"
        : "+f"(d[0]), "+f"(d[1]), "+f"(d[2]), "+f"(d[3])
        : "r"(a[0]), "r"(a[1]), "r"(a[2]), "r"(a[3]), "r"(b0), "r"(b1));
}

// ---------------------------------------------------------------------------
__global__ void prep_params(const float* __restrict__ lr,
                            const float* __restrict__ li,
                            const float* __restrict__ delta) {
    int p = threadIdx.x;
    float step = expf(delta[p]);
    float hs = 0.5f * step;
    float dr = 1.0f - hs * lr[p];
    float di = -hs * li[p];
    float inv = 1.0f / (dr * dr + di * di);
    float2 BL = make_float2(dr * inv, -di * inv);
    float2 num = make_float2(1.0f + hs * lr[p], hs * li[p]);
    float2 a = cmul(BL, num);
    g_a[p] = a;
    g_Bscale[p] = make_float2(BL.x * step, BL.y * step);
    float2 t = a;
    #pragma unroll
    for (int i = 0; i < SQ_POW; i++) t = cmul(t, t);
    g_aT[p] = t;
}

__global__ void prep_weights(const float* __restrict__ b,
                             const float* __restrict__ c) {
    int p = blockIdx.x;        // 0..255
    int h = threadIdx.x;       // 0..511
    float2 bs = g_Bscale[p];
    float br = b[(p * H_FEAT + h) * 2 + 0];
    float bi = b[(p * H_FEAT + h) * 2 + 1];
    // W1 as [n=2p|2p+1][k=h]  (mma B operand: [N][K], K contiguous)
    g_W1h[(2 * p) * H_FEAT + h]     = __float2half_rn(bs.x * br - bs.y * bi);
    g_W1h[(2 * p + 1) * H_FEAT + h] = __float2half_rn(bs.x * bi + bs.y * br);
    // W2 as [n=h][k=2p|2p+1]
    g_W2h[h * N2 + 2 * p]     = __float2half_rn( 2.0f * c[(h * P_STATE + p) * 2 + 0]);
    g_W2h[h * N2 + 2 * p + 1] = __float2half_rn(-2.0f * c[(h * P_STATE + p) * 2 + 1]);
}

// fp32 -> fp16 (grid-stride, float4 -> uint2)
__global__ void convert_half(const float4* __restrict__ src,
                             uint2* __restrict__ dst, int n4) {
    int stride = gridDim.x * blockDim.x;
    for (int i = blockIdx.x * blockDim.x + threadIdx.x; i < n4; i += stride) {
        float4 v = src[i];
        __half2 h0 = __floats2half2_rn(v.x, v.y);
        __half2 h1 = __floats2half2_rn(v.z, v.w);
        dst[i] = make_uint2(*(uint32_t*)&h0, *(uint32_t*)&h1);
    }
}

// ---------------------------------------------------------------------------
// fp16 GEMM: C[M,512] = A[M,K] x B[N,K]^T (single-rounded fp16, f32 accum)
// block 128x128, 256 thr, warp 32x64, K-chunks 32, 3-stage cp.async
// MODE 0: write half2 -> g_BuH   MODE 1: fp32 out + d*u epilogue
// ---------------------------------------------------------------------------
template <int MODE>
__global__ void __launch_bounds__(256, 1)
gemm_fp16(const __half* __restrict__ Ah, const __half* __restrict__ Bw,
          float* __restrict__ Cout, const float* __restrict__ U,
          const float* __restrict__ D) {
    extern __shared__ char smem[];
    const uint32_t sb = smem_u32(smem);
    const int tid = threadIdx.x;
    const int wid = tid >> 5, lane = tid & 31;
    const int warpM = wid & 3, warpN = wid >> 2;       // 4x2 warp grid
    const int bm = blockIdx.y * BM;
    const int bn = blockIdx.x * BN;

    const char* baseA = (const char*)Ah + (size_t)bm * 1024;
    const char* baseB = (const char*)Bw + (size_t)bn * 1024;

    auto load_chunk = [&](int kt, int st) {
        const uint32_t base = sb + st * STG_BYTES;
        const int kb = kt * 64;                        // byte offset into row
        const int s = tid & 3;
        #pragma unroll
        for (int j = 0; j < 4; j++) {
            const int op = j >> 1;
            const int r = (tid >> 2) + ((j & 1) << 6);
            cp16(base + op * OP_BYTES + r * ROWB + s * 16,
                 (op ? baseB : baseA) + (size_t)r * 1024 + kb + s * 16);
        }
        asm volatile("cp.async.commit_group;");
    };

    load_chunk(0, 0);
    load_chunk(1, 1);

    float acc[2][8][4];
    #pragma unroll
    for (int im = 0; im < 2; im++)
        #pragma unroll
        for (int in = 0; in < 8; in++)
            #pragma unroll
            for (int q = 0; q < 4; q++) acc[im][in][q] = 0.0f;

    const uint32_t a_lo = (lane & 15) * ROWB + (lane >> 4) * 16;
    const uint32_t b_lo = ((lane & 7) + ((lane >> 4) << 3)) * ROWB +
                          ((lane >> 3) & 1) * 16;

    for (int kt = 0; kt < NCH; kt++) {
        const int st = kt % NSTAGE;
        if (kt == NCH - 1) asm volatile("cp.async.wait_group 0;");
        else               asm volatile("cp.async.wait_group 1;");
        __syncthreads();
        if (kt + 2 < NCH) load_chunk(kt + 2, (kt + 2) % NSTAGE);

        const uint32_t sg = sb + st * STG_BYTES;
        #pragma unroll
        for (int ks = 0; ks < 2; ks++) {
            const uint32_t ksb = ks * 32;
            uint32_t ah[2][4], bh[4][4];
            #pragma unroll
            for (int im = 0; im < 2; im++) {
                const uint32_t ao = (warpM * 32 + im * 16) * ROWB + a_lo + ksb;
                ldsm4(ah[im], sg + ao);
            }
            #pragma unroll
            for (int ip = 0; ip < 4; ip++) {
                const uint32_t bo = (warpN * 64 + ip * 16) * ROWB + b_lo + ksb;
                ldsm4(bh[ip], sg + OP_BYTES + bo);
            }
            #pragma unroll
            for (int im = 0; im < 2; im++)
                #pragma unroll
                for (int ip = 0; ip < 4; ip++) {
                    mma_f32(acc[im][2 * ip],     ah[im], bh[ip][0], bh[ip][1]);
                    mma_f32(acc[im][2 * ip + 1], ah[im], bh[ip][2], bh[ip][3]);
                }
        }
    }

    #pragma unroll
    for (int im = 0; im < 2; im++) {
        const int row0 = bm + warpM * 32 + im * 16 + (lane >> 2);
        #pragma unroll
        for (int in = 0; in < 8; in++) {
            const int col = bn + warpN * 64 + in * 8 + (lane & 3) * 2;
            if constexpr (MODE == 0) {
                // col is even; (col, col+1) = (re, im) of state p = col/2
                __half2 h0 = __floats2half2_rn(acc[im][in][0], acc[im][in][1]);
                __half2 h1 = __floats2half2_rn(acc[im][in][2], acc[im][in][3]);
                g_BuH[(size_t)row0 * P_STATE + (col >> 1)]       = *(uint32_t*)&h0;
                g_BuH[(size_t)(row0 + 8) * P_STATE + (col >> 1)] = *(uint32_t*)&h1;
            } else {
                float2 v0 = make_float2(acc[im][in][0], acc[im][in][1]);
                float2 v1 = make_float2(acc[im][in][2], acc[im][in][3]);
                float2 dv = *(const float2*)&D[col];
                float2 u0 = *(const float2*)&U[(size_t)row0 * H_FEAT + col];
                float2 u1 = *(const float2*)&U[(size_t)(row0 + 8) * H_FEAT + col];
                v0.x = fmaf(dv.x, u0.x, v0.x); v0.y = fmaf(dv.y, u0.y, v0.y);
                v1.x = fmaf(dv.x, u1.x, v1.x); v1.y = fmaf(dv.y, u1.y, v1.y);
                *(float2*)&Cout[(size_t)row0 * H_FEAT + col] = v0;
                *(float2*)&Cout[(size_t)(row0 + 8) * H_FEAT + col] = v1;
            }
        }
    }
}

// ---------------------------------------------------------------------------
// Scan stage 1: per-chunk end states only (fp16 Bu input, fp32 recurrence)
// ---------------------------------------------------------------------------
__global__ void __launch_bounds__(256) ends_kernel() {
    const int p = threadIdx.x;
    const int c = blockIdx.x;
    const float2 a = g_a[p];
    float2 x = make_float2(0.0f, 0.0f);
    size_t base = (size_t)c * T_CHUNK * P_STATE + p;
    #pragma unroll 8
    for (int t = 0; t < T_CHUNK; t++) {
        uint32_t w = g_BuH[base + (size_t)t * P_STATE];
        float2 v = __half22float2(*(__half2*)&w);
        float xr = fmaf(a.x, x.x, fmaf(-a.y, x.y, v.x));
        float xi = fmaf(a.x, x.y, fmaf(a.y, x.x, v.y));
        x = make_float2(xr, xi);
    }
    g_end[c * P_STATE + p] = x;
}

// Stage 2: Kogge-Stone inclusive scan of ends; g_carry[c] = state entering c
__global__ void __launch_bounds__(C_CHUNKS) carry_kernel() {
    __shared__ float2 s[C_CHUNKS];
    const int p = blockIdx.x;
    const int c = threadIdx.x;
    const float2 aT = g_aT[p];
    s[c] = g_end[c * P_STATE + p];
    float2 m = aT;
    __syncthreads();
    for (int d = 1; d < C_CHUNKS; d <<= 1) {
        float2 other = make_float2(0.0f, 0.0f);
        if (c >= d) other = s[c - d];
        __syncthreads();
        if (c >= d) {
            float2 cur = s[c];
            s[c] = make_float2(cur.x + m.x * other.x - m.y * other.y,
                               cur.y + m.x * other.y + m.y * other.x);
        }
        m = cmul(m, m);
        __syncthreads();
    }
    float2 ci = make_float2(0.0f, 0.0f);
    if (c > 0) ci = s[c - 1];
    g_carry[c * P_STATE + p] = ci;
}

// Stage 3: rescan with carry init; write fp16 states to g_Ah
__global__ void __launch_bounds__(256) rescan_convert_kernel() {
    const int p = threadIdx.x;
    const int c = blockIdx.x;
    const float2 a = g_a[p];
    float2 x = g_carry[c * P_STATE + p];             // state entering chunk c
    const size_t base = (size_t)c * T_CHUNK * P_STATE + p;
    uint32_t* hi = (uint32_t*)g_Ah;
    #pragma unroll 4
    for (int t = 0; t < T_CHUNK; t++) {
        uint32_t w = g_BuH[base + (size_t)t * P_STATE];
        float2 v = __half22float2(*(__half2*)&w);
        float xr = fmaf(a.x, x.x, fmaf(-a.y, x.y, v.x));
        float xi = fmaf(a.x, x.y, fmaf(a.y, x.x, v.y));
        x = make_float2(xr, xi);
        __half2 h = __floats2half2_rn(x.x, x.y);
        hi[base + (size_t)t * P_STATE] = *(uint32_t*)&h;   // idx == l*256 + p
    }
}

// ---------------------------------------------------------------------------
extern "C" void kernel_launch(void* const* d_in, const int* in_sizes, int n_in,
                              void* d_out, int out_size) {
    const float* u     = (const float*)d_in[0];
    const float* lr    = (const float*)d_in[1];
    const float* li    = (const float*)d_in[2];
    const float* b     = (const float*)d_in[3];
    const float* c     = (const float*)d_in[4];
    const float* d     = (const float*)d_in[5];
    const float* delta = (const float*)d_in[6];
    float* out = (float*)d_out;

    __half* ah;        cudaGetSymbolAddress((void**)&ah, g_Ah);
    __half* w1h;       cudaGetSymbolAddress((void**)&w1h, g_W1h);
    __half* w2h;       cudaGetSymbolAddress((void**)&w2h, g_W2h);

    cudaFuncSetAttribute(gemm_fp16<0>, cudaFuncAttributeMaxDynamicSharedMemorySize, SMEMB);
    cudaFuncSetAttribute(gemm_fp16<1>, cudaFuncAttributeMaxDynamicSharedMemorySize, SMEMB);

    const int N4 = L_SEQ * N2 / 4;

    prep_params<<<1, P_STATE>>>(lr, li, delta);
    prep_weights<<<P_STATE, H_FEAT>>>(b, c);
    convert_half<<<2048, 256>>>((const float4*)u, (uint2*)ah, N4);
    gemm_fp16<0><<<dim3(N2 / BN, L_SEQ / BM), 256, SMEMB>>>(
        ah, w1h, nullptr, nullptr, nullptr);
    ends_kernel<<<C_CHUNKS, P_STATE>>>();
    carry_kernel<<<P_STATE, C_CHUNKS>>>();
    rescan_convert_kernel<<<C_CHUNKS, P_STATE>>>();
    gemm_fp16<1><<<dim3(H_FEAT / BN, L_SEQ / BM), 256, SMEMB>>>(
        ah, w2h, out, u, d);
}